// round 10
// baseline (speedup 1.0000x reference)
#include <cuda_runtime.h>

#define Bn 128
#define Ln 1024
#define INF_ 136
#define F1 256
#define F2 512
#define Hn 256
#define G4 1024

// ---- scratch (device globals) ----
__device__ float g_W1T[INF_ * F1];
__device__ float g_W2T[F1 * F2];
__device__ float g_W4_0[(size_t)F2 * G4];   // packed [k][256][4]
__device__ float g_W4_1[(size_t)Hn * G4];
__device__ float g_W4_2[(size_t)Hn * G4];
__device__ float g_bsum0[G4];
__device__ float g_bsum1[G4];
__device__ float g_bsum2[G4];
__device__ float g_feat[(size_t)Ln * Bn * F2];   // [t][b][512]
__device__ float g_xg[(size_t)Ln * Bn * G4];     // [t*B+b][1024]
__device__ float g_hA[(size_t)Ln * Bn * Hn];
__device__ float g_hB[(size_t)Ln * Bn * Hn];
__device__ float g_hst[3][4][2][8192];           // [layer][rowgroup][pingpong][unit*32+row]
__device__ unsigned g_grpctr[3][4 * 32];         // [layer][rowgroup*32]

// ---- f32x2 packed FMA ----
union F2U { float2 f; unsigned long long u; };
__device__ __forceinline__ float2 ffma2(float2 a, float2 b, float2 c) {
    F2U A, B, C, D;
    A.f = a; B.f = b; C.f = c;
    asm("fma.rn.f32x2 %0, %1, %2, %3;" : "=l"(D.u) : "l"(A.u), "l"(B.u), "l"(C.u));
    return D.f;
}

__device__ __forceinline__ float fast_sigmoid(float x) {
    return 1.f / (1.f + __expf(-x));
}
__device__ __forceinline__ float fast_tanh(float x) {
    return 2.f / (1.f + __expf(-2.f * x)) - 1.f;
}

__device__ __forceinline__ void bar_release(unsigned* ctr) {
    asm volatile("red.release.gpu.global.add.u32 [%0], %1;" :: "l"(ctr), "r"(1u) : "memory");
}
__device__ __forceinline__ void bar_poll(unsigned* ctr, unsigned target) {
    unsigned v;
    do {
        asm volatile("ld.acquire.gpu.global.u32 %0, [%1];" : "=r"(v) : "l"(ctr) : "memory");
    } while (v < target);
}

// ---- fused prep ----
#define N1 (INF_ * F1)
#define N2 (F1 * F2)
#define N3 (F2 * G4)
#define N4 (Hn * G4)
#define NHST (3 * 4 * 8192)
__global__ void prep_kernel(const float* __restrict__ W1, const float* __restrict__ W2,
                            const float* __restrict__ w_ih0, const float* __restrict__ w_ih1,
                            const float* __restrict__ w_ih2,
                            const float* __restrict__ b_ih0, const float* __restrict__ b_hh0,
                            const float* __restrict__ b_ih1, const float* __restrict__ b_hh1,
                            const float* __restrict__ b_ih2, const float* __restrict__ b_hh2) {
    int i = blockIdx.x * blockDim.x + threadIdx.x;
    if (i < N1) {
        int r = i / INF_, c = i % INF_;
        g_W1T[c * F1 + r] = W1[i];
        return;
    }
    i -= N1;
    if (i < N2) {
        int r = i / F1, c = i % F1;
        g_W2T[c * F2 + r] = W2[i];
        return;
    }
    i -= N2;
    if (i < N3) {
        int k = i >> 10, rem = i & 1023, c = rem >> 2, g = rem & 3;
        g_W4_0[i] = w_ih0[(size_t)(g * 256 + c) * F2 + k];
        return;
    }
    i -= N3;
    if (i < N4) {
        int k = i >> 10, rem = i & 1023, c = rem >> 2, g = rem & 3;
        g_W4_1[i] = w_ih1[(size_t)(g * 256 + c) * Hn + k];
        return;
    }
    i -= N4;
    if (i < N4) {
        int k = i >> 10, rem = i & 1023, c = rem >> 2, g = rem & 3;
        g_W4_2[i] = w_ih2[(size_t)(g * 256 + c) * Hn + k];
        return;
    }
    i -= N4;
    if (i < G4) { g_bsum0[i] = b_ih0[i] + b_hh0[i]; return; }
    i -= G4;
    if (i < G4) { g_bsum1[i] = b_ih1[i] + b_hh1[i]; return; }
    i -= G4;
    if (i < G4) { g_bsum2[i] = b_ih2[i] + b_hh2[i]; return; }
    i -= G4;
    if (i < 3 * 128) { (&g_grpctr[0][0])[i] = 0u; return; }
    i -= 3 * 128;
    if (i < NHST) {
        int l = i >> 15;
        int rem = i & 32767;
        int rg = rem >> 13;
        int j = rem & 8191;
        g_hst[l][rg][0][j] = 0.f;
        return;
    }
}
#define PREP_TOTAL (N1 + N2 + N3 + 2 * N4 + 3 * G4 + 3 * 128 + NHST)

// ---- MLP v2 (unchanged, passing) ----
#define H1P 18
__global__ __launch_bounds__(256) void mlp2_kernel(const float* __restrict__ x,
                                                   const float* __restrict__ b1,
                                                   const float* __restrict__ b2) {
    __shared__ float xs[INF_ * 16];
    __shared__ float h1s[F1 * H1P];
    const int tid = threadIdx.x;
    const size_t row0 = (size_t)blockIdx.x * 16;

    const float* xr = x + row0 * INF_;
    for (int idx = tid; idx < 16 * INF_; idx += 256) {
        int r = idx / INF_, k = idx % INF_;
        xs[k * 16 + r] = xr[idx];
    }
    __syncthreads();

    {
        float2 acc[8];
        const float bb = b1[tid];
#pragma unroll
        for (int p = 0; p < 8; ++p) acc[p] = make_float2(bb, bb);
#pragma unroll 2
        for (int k = 0; k < INF_; ++k) {
            float w = g_W1T[k * F1 + tid];
            float2 w2 = make_float2(w, w);
            const float4* xp = (const float4*)(xs + k * 16);
#pragma unroll
            for (int q = 0; q < 4; ++q) {
                float4 v = xp[q];
                acc[2 * q]     = ffma2(make_float2(v.x, v.y), w2, acc[2 * q]);
                acc[2 * q + 1] = ffma2(make_float2(v.z, v.w), w2, acc[2 * q + 1]);
            }
        }
        float* hp = h1s + tid * H1P;
#pragma unroll
        for (int p = 0; p < 8; ++p) {
            *(float2*)(hp + 2 * p) = make_float2(fmaxf(acc[p].x, 0.f), fmaxf(acc[p].y, 0.f));
        }
    }
    __syncthreads();

    {
        float2 acc0[8], acc1[8];
        const float bb0 = b2[tid], bb1 = b2[tid + 256];
#pragma unroll
        for (int p = 0; p < 8; ++p) { acc0[p] = make_float2(bb0, bb0); acc1[p] = make_float2(bb1, bb1); }
#pragma unroll 2
        for (int k = 0; k < F1; ++k) {
            float w0 = g_W2T[k * F2 + tid];
            float w1 = g_W2T[k * F2 + tid + 256];
            float2 w20 = make_float2(w0, w0);
            float2 w21 = make_float2(w1, w1);
            const float* hp = h1s + k * H1P;
#pragma unroll
            for (int p = 0; p < 8; ++p) {
                float2 a = *(const float2*)(hp + 2 * p);
                acc0[p] = ffma2(a, w20, acc0[p]);
                acc1[p] = ffma2(a, w21, acc1[p]);
            }
        }
#pragma unroll
        for (int p = 0; p < 8; ++p) {
#pragma unroll
            for (int h = 0; h < 2; ++h) {
                size_t row = row0 + 2 * p + h;
                int b_ = (int)(row / Ln), t_ = (int)(row % Ln);
                float* fp = g_feat + ((size_t)t_ * Bn + b_) * F2;
                float v0 = h ? acc0[p].y : acc0[p].x;
                float v1 = h ? acc1[p].y : acc1[p].x;
                fp[tid] = fmaxf(v0, 0.f);
                fp[tid + 256] = fmaxf(v1, 0.f);
            }
        }
    }
}

// ---- xg GEMM (unchanged, passing) ----
template <int K, bool SRC_KMAJOR>
__global__ __launch_bounds__(256, 1) void xg2_kernel(const float* __restrict__ A,
                                                     const float* __restrict__ W4,
                                                     const float* __restrict__ bsum,
                                                     float* __restrict__ out) {
    extern __shared__ float As[];  // [K][36]
    const int tid = threadIdx.x;
    const int row0 = blockIdx.x * 32;

    if (SRC_KMAJOR) {
        const int t = row0 >> 7, b0 = row0 & 127;
        const float* base = A + ((size_t)t * K) * 128 + b0;
        for (int i = tid; i < K * 8; i += 256) {
            int k = i >> 3, r4 = (i & 7) * 4;
            *(float4*)(As + k * 36 + r4) = *(const float4*)(base + (size_t)k * 128 + r4);
        }
    } else {
        constexpr int KQ = K / 4;
        for (int i = tid; i < 32 * KQ; i += 256) {
            int r = i / KQ, kq = i % KQ;
            float4 v = *(const float4*)(A + (size_t)(row0 + r) * K + kq * 4);
            As[(kq * 4 + 0) * 36 + r] = v.x;
            As[(kq * 4 + 1) * 36 + r] = v.y;
            As[(kq * 4 + 2) * 36 + r] = v.z;
            As[(kq * 4 + 3) * 36 + r] = v.w;
        }
    }
    __syncthreads();

    float2 acc[16][4];
#pragma unroll
    for (int p = 0; p < 16; ++p)
#pragma unroll
        for (int g = 0; g < 4; ++g) acc[p][g] = make_float2(0.f, 0.f);

    const float4* wp = (const float4*)W4 + tid;
#pragma unroll 2
    for (int k = 0; k < K; ++k) {
        float4 w4 = wp[(size_t)k * 256];
        float2 w2[4];
        w2[0] = make_float2(w4.x, w4.x);
        w2[1] = make_float2(w4.y, w4.y);
        w2[2] = make_float2(w4.z, w4.z);
        w2[3] = make_float2(w4.w, w4.w);
        const float4* ap = (const float4*)(As + k * 36);
#pragma unroll
        for (int q = 0; q < 8; ++q) {
            float4 a4 = ap[q];
            float2 alo = make_float2(a4.x, a4.y);
            float2 ahi = make_float2(a4.z, a4.w);
#pragma unroll
            for (int g = 0; g < 4; ++g) {
                acc[2 * q][g]     = ffma2(alo, w2[g], acc[2 * q][g]);
                acc[2 * q + 1][g] = ffma2(ahi, w2[g], acc[2 * q + 1][g]);
            }
        }
    }

    float bb[4];
#pragma unroll
    for (int g = 0; g < 4; ++g) bb[g] = bsum[tid + g * 256];
#pragma unroll
    for (int p = 0; p < 16; ++p) {
        float* o0 = out + (size_t)(row0 + 2 * p) * G4 + tid;
        float* o1 = o0 + G4;
#pragma unroll
        for (int g = 0; g < 4; ++g) {
            o0[g * 256] = acc[p][g].x + bb[g];
            o1[g * 256] = acc[p][g].y + bb[g];
        }
    }
}

// ---- LSTM recurrence v6 (fixed): 2 independent row-group tiles per block ----
#define WSP 260
__device__ __forceinline__ void gemm_tile(const float* __restrict__ h_s,
                                          const float* __restrict__ w_s,
                                          float* __restrict__ gx,
                                          int kq, int c, int r0, float2 i01, float2 i23) {
    float2 a01 = i01, a23 = i23;
    const float* wp = w_s + c * WSP + kq * 64;
    const float* hp = h_s + (kq * 64) * 32 + r0;
#pragma unroll 4
    for (int k = 0; k < 64; k += 4) {
        float4 wv = *(const float4*)(wp + k);
        float4 h0 = *(const float4*)(hp + (k + 0) * 32);
        a01 = ffma2(make_float2(h0.x, h0.y), make_float2(wv.x, wv.x), a01);
        a23 = ffma2(make_float2(h0.z, h0.w), make_float2(wv.x, wv.x), a23);
        float4 h1 = *(const float4*)(hp + (k + 1) * 32);
        a01 = ffma2(make_float2(h1.x, h1.y), make_float2(wv.y, wv.y), a01);
        a23 = ffma2(make_float2(h1.z, h1.w), make_float2(wv.y, wv.y), a23);
        float4 h2 = *(const float4*)(hp + (k + 2) * 32);
        a01 = ffma2(make_float2(h2.x, h2.y), make_float2(wv.z, wv.z), a01);
        a23 = ffma2(make_float2(h2.z, h2.w), make_float2(wv.z, wv.z), a23);
        float4 h3 = *(const float4*)(hp + (k + 3) * 32);
        a01 = ffma2(make_float2(h3.x, h3.y), make_float2(wv.w, wv.w), a01);
        a23 = ffma2(make_float2(h3.z, h3.w), make_float2(wv.w, wv.w), a23);
    }
    *(float4*)(gx + kq * 576 + c * 36 + r0) = make_float4(a01.x, a01.y, a23.x, a23.y);
}

template <bool OUT_TBU>
__global__ __launch_bounds__(512) void lstm6_kernel(const float* __restrict__ xg,
                                                    const float* __restrict__ w_hh,
                                                    float* __restrict__ hout,
                                                    unsigned* __restrict__ ctrL,
                                                    float* __restrict__ hstL) {
    extern __shared__ float sm[];
    float* w_s = sm;                    // [16 cols][260]
    float* h_s = sm + 16 * WSP;         // [256 units][32 rows]
    float* gx  = sm + 16 * WSP + 8192;  // [4 kq][16 cols][36]

    const int tid = threadIdx.x;
    const int bid = blockIdx.x;
    const int rgA = bid >> 6;           // 0 or 1
    const int rgB = rgA + 2;            // 2 or 3
    const int u0 = (bid & 63) * 4;      // global unit base (4 units per block)

    const int w = tid >> 5;
    const int lane = tid & 31;
    const int kq = w & 3;
    const int wt = w >> 2;
    const int rowhalf = wt & 1;
    const int colhalf = wt >> 1;
    const int c = colhalf * 8 + (lane & 7);            // tile-local gate col 0..15
    const int r0 = rowhalf * 16 + (lane >> 3) * 4;     // tile-local row 0..28
    const int jcol = (c >> 2) * Hn + u0 + (c & 3);     // global gate col

    for (int i = tid; i < 16 * 256; i += 512) {
        int cc = i >> 8, k = i & 255;
        int jc = (cc >> 2) * Hn + u0 + (cc & 3);
        w_s[cc * WSP + k] = w_hh[(size_t)jc * Hn + k];
    }

    const int pu = tid >> 5;   // 0..3 (tid<128)
    const int pr = tid & 31;   // 0..31
    const int hidx = (u0 + pu) * 32 + pr;   // FIXED: block-offset state index
    float cstA = 0.f, cstB = 0.f;

    unsigned* ctrA = ctrL + rgA * 32;
    unsigned* ctrB = ctrL + rgB * 32;

    float xA0 = 0.f, xA1 = 0.f, xA2 = 0.f, xA3 = 0.f;
    float xB0 = 0.f, xB1 = 0.f, xB2 = 0.f, xB3 = 0.f;
    if (kq == 0) {
        const float* pa = xg + ((size_t)rgA * 32 + r0) * G4 + jcol;
        xA0 = pa[0]; xA1 = pa[G4]; xA2 = pa[2 * G4]; xA3 = pa[3 * G4];
        const float* pb = xg + ((size_t)rgB * 32 + r0) * G4 + jcol;
        xB0 = pb[0]; xB1 = pb[G4]; xB2 = pb[2 * G4]; xB3 = pb[3 * G4];
    }

    __syncthreads();

    for (int t = 0; t < Ln; ++t) {
        // ======== tile A (rowgroup rgA) ========
        {
            const float4* src = (const float4*)(hstL + (size_t)(rgA * 2 + (t & 1)) * 8192);
            float4* dst = (float4*)h_s;
#pragma unroll
            for (int i = 0; i < 4; ++i) dst[tid + i * 512] = src[tid + i * 512];
        }
        __syncthreads();

        gemm_tile(h_s, w_s, gx, kq, c, r0,
                  kq == 0 ? make_float2(xA0, xA1) : make_float2(0.f, 0.f),
                  kq == 0 ? make_float2(xA2, xA3) : make_float2(0.f, 0.f));
        __syncthreads();

        if (tid < 128) {
            float iv = gx[0 * 576 + (0 + pu) * 36 + pr]  + gx[1 * 576 + (0 + pu) * 36 + pr]
                     + gx[2 * 576 + (0 + pu) * 36 + pr]  + gx[3 * 576 + (0 + pu) * 36 + pr];
            float fv = gx[0 * 576 + (4 + pu) * 36 + pr]  + gx[1 * 576 + (4 + pu) * 36 + pr]
                     + gx[2 * 576 + (4 + pu) * 36 + pr]  + gx[3 * 576 + (4 + pu) * 36 + pr];
            float gv = gx[0 * 576 + (8 + pu) * 36 + pr]  + gx[1 * 576 + (8 + pu) * 36 + pr]
                     + gx[2 * 576 + (8 + pu) * 36 + pr]  + gx[3 * 576 + (8 + pu) * 36 + pr];
            float ov = gx[0 * 576 + (12 + pu) * 36 + pr] + gx[1 * 576 + (12 + pu) * 36 + pr]
                     + gx[2 * 576 + (12 + pu) * 36 + pr] + gx[3 * 576 + (12 + pu) * 36 + pr];
            iv = fast_sigmoid(iv);
            fv = fast_sigmoid(fv);
            gv = fast_tanh(gv);
            ov = fast_sigmoid(ov);
            cstA = fv * cstA + iv * gv;
            float hv = ov * fast_tanh(cstA);
            hstL[(size_t)(rgA * 2 + ((t + 1) & 1)) * 8192 + hidx] = hv;
            if (OUT_TBU)
                hout[((size_t)t * Bn + rgA * 32 + pr) * Hn + u0 + pu] = hv;
            else
                hout[((size_t)t * Hn + u0 + pu) * Bn + rgA * 32 + pr] = hv;
        }
        if (kq == 0 && t + 1 < Ln) {
            const float* pa = xg + ((size_t)(t + 1) * Bn + rgA * 32 + r0) * G4 + jcol;
            xA0 = pa[0]; xA1 = pa[G4]; xA2 = pa[2 * G4]; xA3 = pa[3 * G4];
        }
        __syncthreads();
        if (tid == 0) bar_release(ctrA);
        if (tid == 32) bar_poll(ctrB, (unsigned)t * 64u);
        __syncthreads();

        // ======== tile B (rowgroup rgB) ========
        {
            const float4* src = (const float4*)(hstL + (size_t)(rgB * 2 + (t & 1)) * 8192);
            float4* dst = (float4*)h_s;
#pragma unroll
            for (int i = 0; i < 4; ++i) dst[tid + i * 512] = src[tid + i * 512];
        }
        __syncthreads();

        gemm_tile(h_s, w_s, gx, kq, c, r0,
                  kq == 0 ? make_float2(xB0, xB1) : make_float2(0.f, 0.f),
                  kq == 0 ? make_float2(xB2, xB3) : make_float2(0.f, 0.f));
        __syncthreads();

        if (tid < 128) {
            float iv = gx[0 * 576 + (0 + pu) * 36 + pr]  + gx[1 * 576 + (0 + pu) * 36 + pr]
                     + gx[2 * 576 + (0 + pu) * 36 + pr]  + gx[3 * 576 + (0 + pu) * 36 + pr];
            float fv = gx[0 * 576 + (4 + pu) * 36 + pr]  + gx[1 * 576 + (4 + pu) * 36 + pr]
                     + gx[2 * 576 + (4 + pu) * 36 + pr]  + gx[3 * 576 + (4 + pu) * 36 + pr];
            float gv = gx[0 * 576 + (8 + pu) * 36 + pr]  + gx[1 * 576 + (8 + pu) * 36 + pr]
                     + gx[2 * 576 + (8 + pu) * 36 + pr]  + gx[3 * 576 + (8 + pu) * 36 + pr];
            float ov = gx[0 * 576 + (12 + pu) * 36 + pr] + gx[1 * 576 + (12 + pu) * 36 + pr]
                     + gx[2 * 576 + (12 + pu) * 36 + pr] + gx[3 * 576 + (12 + pu) * 36 + pr];
            iv = fast_sigmoid(iv);
            fv = fast_sigmoid(fv);
            gv = fast_tanh(gv);
            ov = fast_sigmoid(ov);
            cstB = fv * cstB + iv * gv;
            float hv = ov * fast_tanh(cstB);
            hstL[(size_t)(rgB * 2 + ((t + 1) & 1)) * 8192 + hidx] = hv;
            if (OUT_TBU)
                hout[((size_t)t * Bn + rgB * 32 + pr) * Hn + u0 + pu] = hv;
            else
                hout[((size_t)t * Hn + u0 + pu) * Bn + rgB * 32 + pr] = hv;
        }
        if (kq == 0 && t + 1 < Ln) {
            const float* pb = xg + ((size_t)(t + 1) * Bn + rgB * 32 + r0) * G4 + jcol;
            xB0 = pb[0]; xB1 = pb[G4]; xB2 = pb[2 * G4]; xB3 = pb[3 * G4];
        }
        __syncthreads();
        if (tid == 0) bar_release(ctrB);
        if (tid == 32 && t + 1 < Ln) bar_poll(ctrA, (unsigned)(t + 1) * 64u);
        __syncthreads();
    }
}

// ---- decision head (unchanged) ----
__global__ __launch_bounds__(256) void decision_kernel(const float* __restrict__ hseq,
                                                       const float* __restrict__ Wd,
                                                       const float* __restrict__ bd,
                                                       const int* __restrict__ length,
                                                       float* __restrict__ out) {
    const int b = blockIdx.x;
    const int tid = threadIdx.x;
    const int len = length[b];
    const float w = Wd[tid];
    float s0 = 0.f, s1 = 0.f, s2 = 0.f, s3 = 0.f;
    int t = 0;
    for (; t + 4 <= len; t += 4) {
        s0 = fmaf(hseq[((size_t)(t + 0) * Bn + b) * Hn + tid], w, s0);
        s1 = fmaf(hseq[((size_t)(t + 1) * Bn + b) * Hn + tid], w, s1);
        s2 = fmaf(hseq[((size_t)(t + 2) * Bn + b) * Hn + tid], w, s2);
        s3 = fmaf(hseq[((size_t)(t + 3) * Bn + b) * Hn + tid], w, s3);
    }
    for (; t < len; ++t) s0 = fmaf(hseq[((size_t)t * Bn + b) * Hn + tid], w, s0);
    float s = (s0 + s1) + (s2 + s3);
    __shared__ float red[256];
    red[tid] = s;
    __syncthreads();
    for (int st = 128; st > 0; st >>= 1) {
        if (tid < st) red[tid] += red[tid + st];
        __syncthreads();
    }
    if (tid == 0) out[b] = red[0] / (float)len + bd[0];
}

extern "C" void kernel_launch(void* const* d_in, const int* in_sizes, int n_in,
                              void* d_out, int out_size) {
    const float* x     = (const float*)d_in[0];
    const int* length  = (const int*)d_in[1];
    const float* W1    = (const float*)d_in[2];
    const float* b1    = (const float*)d_in[3];
    const float* W2    = (const float*)d_in[4];
    const float* b2    = (const float*)d_in[5];
    const float* w_ih0 = (const float*)d_in[6];
    const float* w_hh0 = (const float*)d_in[7];
    const float* b_ih0 = (const float*)d_in[8];
    const float* b_hh0 = (const float*)d_in[9];
    const float* w_ih1 = (const float*)d_in[10];
    const float* w_hh1 = (const float*)d_in[11];
    const float* b_ih1 = (const float*)d_in[12];
    const float* b_hh1 = (const float*)d_in[13];
    const float* w_ih2 = (const float*)d_in[14];
    const float* w_hh2 = (const float*)d_in[15];
    const float* b_ih2 = (const float*)d_in[16];
    const float* b_hh2 = (const float*)d_in[17];
    const float* Wd    = (const float*)d_in[18];
    const float* bd    = (const float*)d_in[19];
    float* out = (float*)d_out;

    float *dP0, *dP1, *dP2, *dB0, *dB1, *dB2, *dFeat, *dXg, *dHA, *dHB, *dHst;
    unsigned* dCtr;
    cudaGetSymbolAddress((void**)&dP0, g_W4_0);
    cudaGetSymbolAddress((void**)&dP1, g_W4_1);
    cudaGetSymbolAddress((void**)&dP2, g_W4_2);
    cudaGetSymbolAddress((void**)&dB0, g_bsum0);
    cudaGetSymbolAddress((void**)&dB1, g_bsum1);
    cudaGetSymbolAddress((void**)&dB2, g_bsum2);
    cudaGetSymbolAddress((void**)&dFeat, g_feat);
    cudaGetSymbolAddress((void**)&dXg, g_xg);
    cudaGetSymbolAddress((void**)&dHA, g_hA);
    cudaGetSymbolAddress((void**)&dHB, g_hB);
    cudaGetSymbolAddress((void**)&dHst, g_hst);
    cudaGetSymbolAddress((void**)&dCtr, g_grpctr);

    const int xg_smem512 = 512 * 36 * sizeof(float);
    const int xg_smem256 = 256 * 36 * sizeof(float);
    const int lstm_smem = (16 * WSP + 8192 + 4 * 16 * 36) * sizeof(float);
    cudaFuncSetAttribute(xg2_kernel<F2, false>, cudaFuncAttributeMaxDynamicSharedMemorySize, xg_smem512);
    cudaFuncSetAttribute(xg2_kernel<Hn, true>, cudaFuncAttributeMaxDynamicSharedMemorySize, xg_smem256);
    cudaFuncSetAttribute(lstm6_kernel<false>, cudaFuncAttributeMaxDynamicSharedMemorySize, lstm_smem);
    cudaFuncSetAttribute(lstm6_kernel<true>, cudaFuncAttributeMaxDynamicSharedMemorySize, lstm_smem);

    prep_kernel<<<(PREP_TOTAL + 255) / 256, 256>>>(W1, W2, w_ih0, w_ih1, w_ih2,
                                                   b_ih0, b_hh0, b_ih1, b_hh1, b_ih2, b_hh2);

    const int nrows = Bn * Ln;
    mlp2_kernel<<<nrows / 16, 256>>>(x, b1, b2);

    // layer 0 (lstm is the 4th launch -> profiled by ncu)
    xg2_kernel<F2, false><<<nrows / 32, 256, xg_smem512>>>(dFeat, dP0, dB0, dXg);
    lstm6_kernel<false><<<128, 512, lstm_smem>>>(dXg, w_hh0, dHA, dCtr + 0 * 128, dHst + 0 * 65536);
    // layer 1
    xg2_kernel<Hn, true><<<nrows / 32, 256, xg_smem256>>>(dHA, dP1, dB1, dXg);
    lstm6_kernel<false><<<128, 512, lstm_smem>>>(dXg, w_hh1, dHB, dCtr + 1 * 128, dHst + 1 * 65536);
    // layer 2
    xg2_kernel<Hn, true><<<nrows / 32, 256, xg_smem256>>>(dHB, dP2, dB2, dXg);
    lstm6_kernel<true><<<128, 512, lstm_smem>>>(dXg, w_hh2, dHA, dCtr + 2 * 128, dHst + 2 * 65536);

    decision_kernel<<<Bn, 256>>>(dHA, Wd, bd, length, out);
}

// round 11
// speedup vs baseline: 1.1811x; 1.1811x over previous
#include <cuda_runtime.h>

#define Bn 128
#define Ln 1024
#define INF_ 136
#define F1 256
#define F2 512
#define Hn 256
#define G4 1024
#define WSP 260

// ---- scratch (device globals) ----
__device__ float g_W1T[INF_ * F1];
__device__ float g_W2T[F1 * F2];
__device__ float g_W4_0[(size_t)F2 * G4];   // packed [k][256][4]
__device__ float g_W4_1[(size_t)Hn * G4];
__device__ float g_W4_2[(size_t)Hn * G4];
__device__ float g_bsum0[G4];
__device__ float g_bsum1[G4];
__device__ float g_bsum2[G4];
__device__ float g_feat[(size_t)Ln * Bn * F2];   // [t][b][512]
__device__ float g_xg[(size_t)Ln * Bn * G4];     // [t*B+b][1024]
__device__ float g_hA[(size_t)Ln * Bn * Hn];
__device__ float g_hB[(size_t)Ln * Bn * Hn];
__device__ float g_hst[3][8][2][4096];           // [layer][rowgroup16][pingpong][unit*16+row]
__device__ unsigned g_grpctr[3][8 * 32];         // [layer][rowgroup*32]

// ---- f32x2 packed FMA ----
union F2U { float2 f; unsigned long long u; };
__device__ __forceinline__ float2 ffma2(float2 a, float2 b, float2 c) {
    F2U A, B, C, D;
    A.f = a; B.f = b; C.f = c;
    asm("fma.rn.f32x2 %0, %1, %2, %3;" : "=l"(D.u) : "l"(A.u), "l"(B.u), "l"(C.u));
    return D.f;
}

__device__ __forceinline__ float fast_sigmoid(float x) {
    return 1.f / (1.f + __expf(-x));
}
__device__ __forceinline__ float fast_tanh(float x) {
    return 2.f / (1.f + __expf(-2.f * x)) - 1.f;
}

__device__ __forceinline__ void bar_release(unsigned* ctr) {
    asm volatile("red.release.gpu.global.add.u32 [%0], %1;" :: "l"(ctr), "r"(1u) : "memory");
}
__device__ __forceinline__ void bar_poll(unsigned* ctr, unsigned target) {
    unsigned v;
    do {
        asm volatile("ld.acquire.gpu.global.u32 %0, [%1];" : "=r"(v) : "l"(ctr) : "memory");
    } while (v < target);
}

// ---- fused prep ----
#define N1 (INF_ * F1)
#define N2 (F1 * F2)
#define N3 (F2 * G4)
#define N4 (Hn * G4)
#define NHST (3 * 8 * 4096)
__global__ void prep_kernel(const float* __restrict__ W1, const float* __restrict__ W2,
                            const float* __restrict__ w_ih0, const float* __restrict__ w_ih1,
                            const float* __restrict__ w_ih2,
                            const float* __restrict__ b_ih0, const float* __restrict__ b_hh0,
                            const float* __restrict__ b_ih1, const float* __restrict__ b_hh1,
                            const float* __restrict__ b_ih2, const float* __restrict__ b_hh2) {
    int i = blockIdx.x * blockDim.x + threadIdx.x;
    if (i < N1) {
        int r = i / INF_, c = i % INF_;
        g_W1T[c * F1 + r] = W1[i];
        return;
    }
    i -= N1;
    if (i < N2) {
        int r = i / F1, c = i % F1;
        g_W2T[c * F2 + r] = W2[i];
        return;
    }
    i -= N2;
    if (i < N3) {
        int k = i >> 10, rem = i & 1023, c = rem >> 2, g = rem & 3;
        g_W4_0[i] = w_ih0[(size_t)(g * 256 + c) * F2 + k];
        return;
    }
    i -= N3;
    if (i < N4) {
        int k = i >> 10, rem = i & 1023, c = rem >> 2, g = rem & 3;
        g_W4_1[i] = w_ih1[(size_t)(g * 256 + c) * Hn + k];
        return;
    }
    i -= N4;
    if (i < N4) {
        int k = i >> 10, rem = i & 1023, c = rem >> 2, g = rem & 3;
        g_W4_2[i] = w_ih2[(size_t)(g * 256 + c) * Hn + k];
        return;
    }
    i -= N4;
    if (i < G4) { g_bsum0[i] = b_ih0[i] + b_hh0[i]; return; }
    i -= G4;
    if (i < G4) { g_bsum1[i] = b_ih1[i] + b_hh1[i]; return; }
    i -= G4;
    if (i < G4) { g_bsum2[i] = b_ih2[i] + b_hh2[i]; return; }
    i -= G4;
    if (i < 3 * 256) { (&g_grpctr[0][0])[i] = 0u; return; }
    i -= 3 * 256;
    if (i < NHST) {
        int l = i >> 15;             // /(8*4096)
        int rem = i & 32767;
        int rg = rem >> 12;          // /4096
        int j = rem & 4095;
        g_hst[l][rg][0][j] = 0.f;
        return;
    }
}
#define PREP_TOTAL (N1 + N2 + N3 + 2 * N4 + 3 * G4 + 3 * 256 + NHST)

// ---- MLP v2 (unchanged, passing) ----
#define H1P 18
__global__ __launch_bounds__(256) void mlp2_kernel(const float* __restrict__ x,
                                                   const float* __restrict__ b1,
                                                   const float* __restrict__ b2) {
    __shared__ float xs[INF_ * 16];
    __shared__ float h1s[F1 * H1P];
    const int tid = threadIdx.x;
    const size_t row0 = (size_t)blockIdx.x * 16;

    const float* xr = x + row0 * INF_;
    for (int idx = tid; idx < 16 * INF_; idx += 256) {
        int r = idx / INF_, k = idx % INF_;
        xs[k * 16 + r] = xr[idx];
    }
    __syncthreads();

    {
        float2 acc[8];
        const float bb = b1[tid];
#pragma unroll
        for (int p = 0; p < 8; ++p) acc[p] = make_float2(bb, bb);
#pragma unroll 2
        for (int k = 0; k < INF_; ++k) {
            float w = g_W1T[k * F1 + tid];
            float2 w2 = make_float2(w, w);
            const float4* xp = (const float4*)(xs + k * 16);
#pragma unroll
            for (int q = 0; q < 4; ++q) {
                float4 v = xp[q];
                acc[2 * q]     = ffma2(make_float2(v.x, v.y), w2, acc[2 * q]);
                acc[2 * q + 1] = ffma2(make_float2(v.z, v.w), w2, acc[2 * q + 1]);
            }
        }
        float* hp = h1s + tid * H1P;
#pragma unroll
        for (int p = 0; p < 8; ++p) {
            *(float2*)(hp + 2 * p) = make_float2(fmaxf(acc[p].x, 0.f), fmaxf(acc[p].y, 0.f));
        }
    }
    __syncthreads();

    {
        float2 acc0[8], acc1[8];
        const float bb0 = b2[tid], bb1 = b2[tid + 256];
#pragma unroll
        for (int p = 0; p < 8; ++p) { acc0[p] = make_float2(bb0, bb0); acc1[p] = make_float2(bb1, bb1); }
#pragma unroll 2
        for (int k = 0; k < F1; ++k) {
            float w0 = g_W2T[k * F2 + tid];
            float w1 = g_W2T[k * F2 + tid + 256];
            float2 w20 = make_float2(w0, w0);
            float2 w21 = make_float2(w1, w1);
            const float* hp = h1s + k * H1P;
#pragma unroll
            for (int p = 0; p < 8; ++p) {
                float2 a = *(const float2*)(hp + 2 * p);
                acc0[p] = ffma2(a, w20, acc0[p]);
                acc1[p] = ffma2(a, w21, acc1[p]);
            }
        }
#pragma unroll
        for (int p = 0; p < 8; ++p) {
#pragma unroll
            for (int h = 0; h < 2; ++h) {
                size_t row = row0 + 2 * p + h;
                int b_ = (int)(row / Ln), t_ = (int)(row % Ln);
                float* fp = g_feat + ((size_t)t_ * Bn + b_) * F2;
                float v0 = h ? acc0[p].y : acc0[p].x;
                float v1 = h ? acc1[p].y : acc1[p].x;
                fp[tid] = fmaxf(v0, 0.f);
                fp[tid + 256] = fmaxf(v1, 0.f);
            }
        }
    }
}

// ---- xg GEMM (unchanged, passing) ----
template <int K, bool SRC_KMAJOR>
__global__ __launch_bounds__(256, 1) void xg2_kernel(const float* __restrict__ A,
                                                     const float* __restrict__ W4,
                                                     const float* __restrict__ bsum,
                                                     float* __restrict__ out) {
    extern __shared__ float As[];  // [K][36]
    const int tid = threadIdx.x;
    const int row0 = blockIdx.x * 32;

    if (SRC_KMAJOR) {
        const int t = row0 >> 7, b0 = row0 & 127;
        const float* base = A + ((size_t)t * K) * 128 + b0;
        for (int i = tid; i < K * 8; i += 256) {
            int k = i >> 3, r4 = (i & 7) * 4;
            *(float4*)(As + k * 36 + r4) = *(const float4*)(base + (size_t)k * 128 + r4);
        }
    } else {
        constexpr int KQ = K / 4;
        for (int i = tid; i < 32 * KQ; i += 256) {
            int r = i / KQ, kq = i % KQ;
            float4 v = *(const float4*)(A + (size_t)(row0 + r) * K + kq * 4);
            As[(kq * 4 + 0) * 36 + r] = v.x;
            As[(kq * 4 + 1) * 36 + r] = v.y;
            As[(kq * 4 + 2) * 36 + r] = v.z;
            As[(kq * 4 + 3) * 36 + r] = v.w;
        }
    }
    __syncthreads();

    float2 acc[16][4];
#pragma unroll
    for (int p = 0; p < 16; ++p)
#pragma unroll
        for (int g = 0; g < 4; ++g) acc[p][g] = make_float2(0.f, 0.f);

    const float4* wp = (const float4*)W4 + tid;
#pragma unroll 2
    for (int k = 0; k < K; ++k) {
        float4 w4 = wp[(size_t)k * 256];
        float2 w2[4];
        w2[0] = make_float2(w4.x, w4.x);
        w2[1] = make_float2(w4.y, w4.y);
        w2[2] = make_float2(w4.z, w4.z);
        w2[3] = make_float2(w4.w, w4.w);
        const float4* ap = (const float4*)(As + k * 36);
#pragma unroll
        for (int q = 0; q < 8; ++q) {
            float4 a4 = ap[q];
            float2 alo = make_float2(a4.x, a4.y);
            float2 ahi = make_float2(a4.z, a4.w);
#pragma unroll
            for (int g = 0; g < 4; ++g) {
                acc[2 * q][g]     = ffma2(alo, w2[g], acc[2 * q][g]);
                acc[2 * q + 1][g] = ffma2(ahi, w2[g], acc[2 * q + 1][g]);
            }
        }
    }

    float bb[4];
#pragma unroll
    for (int g = 0; g < 4; ++g) bb[g] = bsum[tid + g * 256];
#pragma unroll
    for (int p = 0; p < 16; ++p) {
        float* o0 = out + (size_t)(row0 + 2 * p) * G4 + tid;
        float* o1 = o0 + G4;
#pragma unroll
        for (int g = 0; g < 4; ++g) {
            o0[g * 256] = acc[p][g].x + bb[g];
            o1[g * 256] = acc[p][g].y + bb[g];
        }
    }
}

// ---- LSTM recurrence v7: 256 blocks (~2 CTAs/SM), 8u x 16r tiles, k-split x2 ----
// Block: rowgroup rg = bid>>5 (16 rows), unit group ug = bid&31 (8 units, 32 gate cols).
// 8 warps: khalf = w>>2 (k in [0,128) or [128,256)), wq = w&3 -> gate wq, 8 cols x 16 rows.
template <bool OUT_TBU>
__global__ __launch_bounds__(256) void lstm7_kernel(const float* __restrict__ xg,
                                                    const float* __restrict__ w_hh,
                                                    float* __restrict__ hout,
                                                    unsigned* __restrict__ ctrL,
                                                    float* __restrict__ hstL) {
    extern __shared__ float sm[];
    float* w_s = sm;                     // [32 cols][WSP]
    float* h_s = sm + 32 * WSP;          // [256 k][16 rows]
    float* gx  = sm + 32 * WSP + 4096;   // [2 khalf][32 cols][20]

    const int tid = threadIdx.x;
    const int bid = blockIdx.x;
    const int rg = bid >> 5;             // 0..7
    const int ug = bid & 31;             // 0..31
    const int u0 = ug * 8;
    const int rbase = rg * 16;

    const int w = tid >> 5;
    const int lane = tid & 31;
    const int khalf = w >> 2;
    const int wq = w & 3;                           // gate index
    const int c = wq * 8 + (lane & 7);              // block-local gate col 0..31
    const int r0 = (lane >> 3) * 4;                 // 0,4,8,12
    const int jcol = wq * Hn + u0 + (lane & 7);     // global gate col
    const int kbeg = khalf * 128;
    float* gxM = gx + khalf * 640;

    // stage w_hh (32 cols x 256 k, k-contiguous, WSP stride conflict-free)
    for (int i = tid; i < 32 * 256; i += 256) {
        int cc = i >> 8, k = i & 255;
        int jc = (cc >> 3) * Hn + u0 + (cc & 7);
        w_s[cc * WSP + k] = w_hh[(size_t)jc * Hn + k];
    }

    const int pu = tid >> 4;    // 0..7 (tid<128): unit
    const int pr = tid & 15;    // row 0..15
    float cst = 0.f;
    unsigned* ctr = ctrL + rg * 32;

    // first-step xg prefetch (khalf==0 warps)
    float x0 = 0.f, x1 = 0.f, x2 = 0.f, x3 = 0.f;
    if (khalf == 0) {
        const float* xp = xg + ((size_t)rbase + r0) * G4 + jcol;
        x0 = xp[0]; x1 = xp[G4]; x2 = xp[2 * G4]; x3 = xp[3 * G4];
    }
    __syncthreads();

    for (int t = 0; t < Ln; ++t) {
        // stage h[t]: 4096 floats, straight contiguous copy (global layout == smem layout)
        {
            const float4* src = (const float4*)(hstL + (size_t)(rg * 2 + (t & 1)) * 4096);
            float4* dst = (float4*)h_s;
#pragma unroll
            for (int i = 0; i < 4; ++i) dst[tid + i * 256] = src[tid + i * 256];
        }
        __syncthreads();

        // partial gates over this khalf: 4 rows x 1 col per lane
        float2 a01 = (khalf == 0) ? make_float2(x0, x1) : make_float2(0.f, 0.f);
        float2 a23 = (khalf == 0) ? make_float2(x2, x3) : make_float2(0.f, 0.f);
        const float* wp = w_s + c * WSP + kbeg;
        const float* hp = h_s + kbeg * 16 + r0;
#pragma unroll 4
        for (int k = 0; k < 128; k += 4) {
            float4 wv = *(const float4*)(wp + k);
            float4 h0 = *(const float4*)(hp + (k + 0) * 16);
            a01 = ffma2(make_float2(h0.x, h0.y), make_float2(wv.x, wv.x), a01);
            a23 = ffma2(make_float2(h0.z, h0.w), make_float2(wv.x, wv.x), a23);
            float4 h1 = *(const float4*)(hp + (k + 1) * 16);
            a01 = ffma2(make_float2(h1.x, h1.y), make_float2(wv.y, wv.y), a01);
            a23 = ffma2(make_float2(h1.z, h1.w), make_float2(wv.y, wv.y), a23);
            float4 h2 = *(const float4*)(hp + (k + 2) * 16);
            a01 = ffma2(make_float2(h2.x, h2.y), make_float2(wv.z, wv.z), a01);
            a23 = ffma2(make_float2(h2.z, h2.w), make_float2(wv.z, wv.z), a23);
            float4 h3 = *(const float4*)(hp + (k + 3) * 16);
            a01 = ffma2(make_float2(h3.x, h3.y), make_float2(wv.w, wv.w), a01);
            a23 = ffma2(make_float2(h3.z, h3.w), make_float2(wv.w, wv.w), a23);
        }
        *(float4*)(gxM + c * 20 + r0) = make_float4(a01.x, a01.y, a23.x, a23.y);
        __syncthreads();

        // pointwise: thread (unit pu, row pr), sum the two khalf partials
        if (tid < 128) {
            float iv = gx[(0 * 8 + pu) * 20 + pr] + gx[640 + (0 * 8 + pu) * 20 + pr];
            float fv = gx[(1 * 8 + pu) * 20 + pr] + gx[640 + (1 * 8 + pu) * 20 + pr];
            float gv = gx[(2 * 8 + pu) * 20 + pr] + gx[640 + (2 * 8 + pu) * 20 + pr];
            float ov = gx[(3 * 8 + pu) * 20 + pr] + gx[640 + (3 * 8 + pu) * 20 + pr];
            iv = fast_sigmoid(iv);
            fv = fast_sigmoid(fv);
            gv = fast_tanh(gv);
            ov = fast_sigmoid(ov);
            cst = fv * cst + iv * gv;
            float hv = ov * fast_tanh(cst);
            hstL[(size_t)(rg * 2 + ((t + 1) & 1)) * 4096 + (u0 + pu) * 16 + pr] = hv;
            if (OUT_TBU)
                hout[((size_t)t * Bn + rbase + pr) * Hn + u0 + pu] = hv;
            else
                hout[((size_t)t * Hn + u0 + pu) * Bn + rbase + pr] = hv;
        }

        // prefetch next-step xg
        if (khalf == 0 && t + 1 < Ln) {
            const float* xp = xg + (((size_t)(t + 1)) * Bn + rbase + r0) * G4 + jcol;
            x0 = xp[0]; x1 = xp[G4]; x2 = xp[2 * G4]; x3 = xp[3 * G4];
        }

        __syncthreads();
        if (tid == 0) bar_release(ctr);
        if (tid == 32) bar_poll(ctr, (unsigned)(t + 1) * 32u);
        __syncthreads();
    }
}

// ---- decision head (unchanged) ----
__global__ __launch_bounds__(256) void decision_kernel(const float* __restrict__ hseq,
                                                       const float* __restrict__ Wd,
                                                       const float* __restrict__ bd,
                                                       const int* __restrict__ length,
                                                       float* __restrict__ out) {
    const int b = blockIdx.x;
    const int tid = threadIdx.x;
    const int len = length[b];
    const float w = Wd[tid];
    float s0 = 0.f, s1 = 0.f, s2 = 0.f, s3 = 0.f;
    int t = 0;
    for (; t + 4 <= len; t += 4) {
        s0 = fmaf(hseq[((size_t)(t + 0) * Bn + b) * Hn + tid], w, s0);
        s1 = fmaf(hseq[((size_t)(t + 1) * Bn + b) * Hn + tid], w, s1);
        s2 = fmaf(hseq[((size_t)(t + 2) * Bn + b) * Hn + tid], w, s2);
        s3 = fmaf(hseq[((size_t)(t + 3) * Bn + b) * Hn + tid], w, s3);
    }
    for (; t < len; ++t) s0 = fmaf(hseq[((size_t)t * Bn + b) * Hn + tid], w, s0);
    float s = (s0 + s1) + (s2 + s3);
    __shared__ float red[256];
    red[tid] = s;
    __syncthreads();
    for (int st = 128; st > 0; st >>= 1) {
        if (tid < st) red[tid] += red[tid + st];
        __syncthreads();
    }
    if (tid == 0) out[b] = red[0] / (float)len + bd[0];
}

extern "C" void kernel_launch(void* const* d_in, const int* in_sizes, int n_in,
                              void* d_out, int out_size) {
    const float* x     = (const float*)d_in[0];
    const int* length  = (const int*)d_in[1];
    const float* W1    = (const float*)d_in[2];
    const float* b1    = (const float*)d_in[3];
    const float* W2    = (const float*)d_in[4];
    const float* b2    = (const float*)d_in[5];
    const float* w_ih0 = (const float*)d_in[6];
    const float* w_hh0 = (const float*)d_in[7];
    const float* b_ih0 = (const float*)d_in[8];
    const float* b_hh0 = (const float*)d_in[9];
    const float* w_ih1 = (const float*)d_in[10];
    const float* w_hh1 = (const float*)d_in[11];
    const float* b_ih1 = (const float*)d_in[12];
    const float* b_hh1 = (const float*)d_in[13];
    const float* w_ih2 = (const float*)d_in[14];
    const float* w_hh2 = (const float*)d_in[15];
    const float* b_ih2 = (const float*)d_in[16];
    const float* b_hh2 = (const float*)d_in[17];
    const float* Wd    = (const float*)d_in[18];
    const float* bd    = (const float*)d_in[19];
    float* out = (float*)d_out;

    float *dP0, *dP1, *dP2, *dB0, *dB1, *dB2, *dFeat, *dXg, *dHA, *dHB, *dHst;
    unsigned* dCtr;
    cudaGetSymbolAddress((void**)&dP0, g_W4_0);
    cudaGetSymbolAddress((void**)&dP1, g_W4_1);
    cudaGetSymbolAddress((void**)&dP2, g_W4_2);
    cudaGetSymbolAddress((void**)&dB0, g_bsum0);
    cudaGetSymbolAddress((void**)&dB1, g_bsum1);
    cudaGetSymbolAddress((void**)&dB2, g_bsum2);
    cudaGetSymbolAddress((void**)&dFeat, g_feat);
    cudaGetSymbolAddress((void**)&dXg, g_xg);
    cudaGetSymbolAddress((void**)&dHA, g_hA);
    cudaGetSymbolAddress((void**)&dHB, g_hB);
    cudaGetSymbolAddress((void**)&dHst, g_hst);
    cudaGetSymbolAddress((void**)&dCtr, g_grpctr);

    const int xg_smem512 = 512 * 36 * sizeof(float);
    const int xg_smem256 = 256 * 36 * sizeof(float);
    const int lstm_smem = (32 * WSP + 4096 + 2 * 32 * 20) * sizeof(float);
    cudaFuncSetAttribute(xg2_kernel<F2, false>, cudaFuncAttributeMaxDynamicSharedMemorySize, xg_smem512);
    cudaFuncSetAttribute(xg2_kernel<Hn, true>, cudaFuncAttributeMaxDynamicSharedMemorySize, xg_smem256);
    cudaFuncSetAttribute(lstm7_kernel<false>, cudaFuncAttributeMaxDynamicSharedMemorySize, lstm_smem);
    cudaFuncSetAttribute(lstm7_kernel<true>, cudaFuncAttributeMaxDynamicSharedMemorySize, lstm_smem);

    prep_kernel<<<(PREP_TOTAL + 255) / 256, 256>>>(W1, W2, w_ih0, w_ih1, w_ih2,
                                                   b_ih0, b_hh0, b_ih1, b_hh1, b_ih2, b_hh2);

    const int nrows = Bn * Ln;
    mlp2_kernel<<<nrows / 16, 256>>>(x, b1, b2);

    // layer 0 (lstm is the 4th launch -> profiled by ncu)
    xg2_kernel<F2, false><<<nrows / 32, 256, xg_smem512>>>(dFeat, dP0, dB0, dXg);
    lstm7_kernel<false><<<256, 256, lstm_smem>>>(dXg, w_hh0, dHA, dCtr + 0 * 256, dHst + 0 * (8 * 2 * 4096));
    // layer 1
    xg2_kernel<Hn, true><<<nrows / 32, 256, xg_smem256>>>(dHA, dP1, dB1, dXg);
    lstm7_kernel<false><<<256, 256, lstm_smem>>>(dXg, w_hh1, dHB, dCtr + 1 * 256, dHst + 1 * (8 * 2 * 4096));
    // layer 2
    xg2_kernel<Hn, true><<<nrows / 32, 256, xg_smem256>>>(dHB, dP2, dB2, dXg);
    lstm7_kernel<true><<<256, 256, lstm_smem>>>(dXg, w_hh2, dHA, dCtr + 2 * 256, dHst + 2 * (8 * 2 * 4096));

    decision_kernel<<<Bn, 256>>>(dHA, Wd, bd, length, out);
}